// round 14
// baseline (speedup 1.0000x reference)
#include <cuda_runtime.h>

// GRU persistent v8 = v5 (best, 4619us) with:
//  - atomic-free group barrier: per-CTA monotonic epoch flags (padded lines),
//    st.release arrive, 16-lane parallel ld.acquire polling. No hot line,
//    no release hop, no reset.
//  - x(t+1) LDG issue moved into barrier-A overlap window.
#define SEQLEN 512
#define HPADF  260
#define XPADF  132
#define WT4    1536
#define QBLK   12480

__device__ float    g_h [256 * 256];
__device__ float    g_rh[256 * 256];
__device__ unsigned g_flag[16 * 16 * 32];   // [group16][cta16], 128B padded

__device__ __forceinline__ void ffma2(unsigned long long &a,
                                      unsigned long long x, unsigned long long y) {
    asm("fma.rn.f32x2 %0, %1, %2, %0;" : "+l"(a) : "l"(x), "l"(y));
}
__device__ __forceinline__ float f2sum(unsigned long long v) {
    return __uint_as_float((unsigned)v) + __uint_as_float((unsigned)(v >> 32));
}
__device__ __forceinline__ float sig_(float a) { return 1.0f / (1.0f + __expf(-a)); }
__device__ __forceinline__ float tanh_(float a) { return 2.0f / (1.0f + __expf(-2.0f * a)) - 1.0f; }
__device__ __forceinline__ void barn(int id) {
    asm volatile("bar.sync %0, 128;" :: "r"(id) : "memory");
}
__device__ __forceinline__ void st_rel(unsigned* p, unsigned v) {
    asm volatile("st.release.gpu.global.u32 [%0], %1;" :: "l"(p), "r"(v) : "memory");
}
__device__ __forceinline__ unsigned ld_acq(const unsigned* p) {
    unsigned v;
    asm volatile("ld.acquire.gpu.global.u32 %0, [%1];" : "=r"(v) : "l"(p) : "memory");
    return v;
}

#define ACC2(a, wv, hv) { ffma2(a, (wv).x, (hv).x); ffma2(a, (wv).y, (hv).y); }
#define ZR16(v0,v1,v2,v3,z0,z1,r0,r1) \
    ACC2(az[0],z0,v0); ACC2(az[1],z1,v0); ACC2(az[2],z0,v1); ACC2(az[3],z1,v1); \
    ACC2(az[4],z0,v2); ACC2(az[5],z1,v2); ACC2(az[6],z0,v3); ACC2(az[7],z1,v3); \
    ACC2(ar[0],r0,v0); ACC2(ar[1],r1,v0); ACC2(ar[2],r0,v1); ACC2(ar[3],r1,v1); \
    ACC2(ar[4],r0,v2); ACC2(ar[5],r1,v2); ACC2(ar[6],r0,v3); ACC2(ar[7],r1,v3);
#define C8(v0,v1,v2,v3,c0,c1) \
    ACC2(ac[0],c0,v0); ACC2(ac[1],c1,v0); ACC2(ac[2],c0,v1); ACC2(ac[3],c1,v1); \
    ACC2(ac[4],c0,v2); ACC2(ac[5],c1,v2); ACC2(ac[6],c0,v3); ACC2(ac[7],c1,v3);

// arrive: intra-half barn orders all threads' global writes, then thread0
// publishes the incremented epoch on this CTA's private flag line.
#define GRP_ARRIVE() { barn(nb); \
    if (w == 0) { epoch++; if (l == 0) st_rel(myflag, epoch); } }
// wait: lanes 0..15 of warp 0 poll the 16 member flags in parallel.
#define GRP_WAIT() { \
    if (w == 0) { \
        if (l < 16) { \
            const unsigned* pf = grpflags + l * 32; \
            while ((int)(ld_acq(pf) - epoch) < 0) { } \
        } \
        __syncwarp(); \
    } \
    barn(nb); }

__global__ void __launch_bounds__(256, 1)
gru_persistent(const float* __restrict__ X,
               const float* __restrict__ Wz, const float* __restrict__ bz,
               const float* __restrict__ Wr, const float* __restrict__ br,
               const float* __restrict__ Wc, const float* __restrict__ bc,
               float* __restrict__ out)
{
    extern __shared__ float sm[];
    float* wT = sm;                       // 18432 floats, k-major interleaved
    float* sB = sm + 18432;               // 48
    const int tid  = threadIdx.x;
    const int half = tid >> 7, lt = tid & 127;
    const int w = lt >> 5, l = lt & 31, rr = l & 3, cc = l >> 2;
    const int bt = blockIdx.x & 7, hsb = blockIdx.x >> 3;
    const int bbase = bt * 32 + half * 16, jbase = hsb * 16;
    const int nb = 1 + half;
    float* hb   = sm + 18480 + half * QBLK;
    float* h_s  = hb;                     // 16 x 260
    float* rh_s = hb + 4160;              // 16 x 260
    float* x_s  = hb + 8320;              // 16 x 132
    float* red  = hb + 10432;             // 2048

    const int grp = bt * 2 + half;        // 16 groups of 16 CTAs
    unsigned* grpflags = &g_flag[grp * 512];
    unsigned* myflag   = grpflags + hsb * 32;
    unsigned epoch = 0;
    if (w == 0) epoch = ld_acq(myflag);   // all flags equal at launch

    {   // weights: k-major, col pairs interleaved (slot = (c>>1) + 8*(c&1))
        float4* wp = (float4*)wT;
        for (int idx = tid; idx < 3 * WT4; idx += 256) {
            int g = idx / WT4, rem = idx % WT4, k4 = rem >> 4, c = rem & 15;
            const float4* W4 = (const float4*)((g == 0) ? Wz : (g == 1) ? Wr : Wc);
            wp[(g * 96 + k4) * 16 + ((c >> 1) + 8 * (c & 1))] = W4[(jbase + c) * 96 + k4];
        }
        if (tid < 16) {
            sB[tid] = bz[jbase + tid]; sB[16 + tid] = br[jbase + tid];
            sB[32 + tid] = bc[jbase + tid];
        }
    }
    for (int i = lt; i < 16 * HPADF; i += 128) h_s[i] = 0.0f;   // h0 = 0
    #pragma unroll
    for (int j = 0; j < 4; j++) {
        int idx = lt + 128 * j, row = idx >> 5, c4 = idx & 31;
        *(float4*)(x_s + row * XPADF + c4 * 4) =
            ((const float4*)X)[(size_t)(bbase + row) * (SEQLEN * 32) + c4];
    }
    __syncthreads();

    const ulonglong2* hA = (const ulonglong2*)(h_s + rr * HPADF);
    const ulonglong2* hB = (const ulonglong2*)(h_s + (rr + 4) * HPADF);
    const ulonglong2* hC = (const ulonglong2*)(h_s + (rr + 8) * HPADF);
    const ulonglong2* hD = (const ulonglong2*)(h_s + (rr + 12) * HPADF);
    const ulonglong2* rA = (const ulonglong2*)(rh_s + rr * HPADF);
    const ulonglong2* rB = (const ulonglong2*)(rh_s + (rr + 4) * HPADF);
    const ulonglong2* rC = (const ulonglong2*)(rh_s + (rr + 8) * HPADF);
    const ulonglong2* rD = (const ulonglong2*)(rh_s + (rr + 12) * HPADF);
    const ulonglong2* xA = (const ulonglong2*)(x_s + rr * XPADF);
    const ulonglong2* xB = (const ulonglong2*)(x_s + (rr + 4) * XPADF);
    const ulonglong2* xC = (const ulonglong2*)(x_s + (rr + 8) * XPADF);
    const ulonglong2* xD = (const ulonglong2*)(x_s + (rr + 12) * XPADF);
    const ulonglong2* wzp = (const ulonglong2*)wT + cc;
    const ulonglong2* wrp = wzp + WT4;
    const ulonglong2* wcp = wzp + 2 * WT4;
    const int kw = w * 16, kx = w * 8, sw = w ^ rr;
    const int orow0 = lt >> 4, ocol = lt & 15, orow1 = orow0 + 8;
    const float bzv = sB[ocol], brv = sB[16 + ocol], bcv = sB[32 + ocol];

    unsigned long long az[8], ar[8], ac[8];
    #pragma unroll
    for (int i = 0; i < 8; i++) { az[i] = 0; ar[i] = 0; }
    #pragma unroll 4
    for (int kk = 0; kk < 8; kk++) {            // z/r x-part, t=0
        int k4 = 64 + kx + kk, kq = kx + kk;
        ulonglong2 v0 = xA[kq], v1 = xB[kq], v2 = xC[kq], v3 = xD[kq];
        ulonglong2 z0 = wzp[k4*16], z1 = wzp[k4*16+8];
        ulonglong2 r0 = wrp[k4*16], r1 = wrp[k4*16+8];
        ZR16(v0,v1,v2,v3,z0,z1,r0,r1)
    }

    // anti-phase stagger: half 1 runs 2 dummy phase1-h passes on zeroed h_s
    // (adds exact zeros to az/ar — numeric identity, offsets the halves).
    if (half == 1) {
        #pragma unroll 1
        for (int d = 0; d < 2; d++) {
            #pragma unroll 4
            for (int kk = 0; kk < 16; kk++) {
                int k4 = kw + kk;
                ulonglong2 v0 = hA[k4], v1 = hB[k4], v2 = hC[k4], v3 = hD[k4];
                ulonglong2 z0 = wzp[k4*16], z1 = wzp[k4*16+8];
                ulonglong2 r0 = wrp[k4*16], r1 = wrp[k4*16+8];
                ZR16(v0,v1,v2,v3,z0,z1,r0,r1)
            }
        }
    }

    for (int t = 0; t < SEQLEN; t++) {
        #pragma unroll 4
        for (int kk = 0; kk < 16; kk++) {       // phase1 h-part
            int k4 = kw + kk;
            ulonglong2 v0 = hA[k4], v1 = hB[k4], v2 = hC[k4], v3 = hD[k4];
            ulonglong2 z0 = wzp[k4*16], z1 = wzp[k4*16+8];
            ulonglong2 r0 = wrp[k4*16], r1 = wrp[k4*16+8];
            ZR16(v0,v1,v2,v3,z0,z1,r0,r1)
        }
        #pragma unroll
        for (int i = 0; i < 4; i++)
            #pragma unroll
            for (int e = 0; e < 2; e++) {
                int o = (rr + 4*i) * 16 + 2*cc + e;
                red[(o << 2) + sw]         = f2sum(az[i*2+e]);
                red[((256 + o) << 2) + sw] = f2sum(ar[i*2+e]);
            }
        barn(nb);
        float4 p0 = *(float4*)(red + lt*4);
        float4 p1 = *(float4*)(red + (lt+128)*4);
        float4 p2 = *(float4*)(red + (lt+256)*4);
        float4 p3 = *(float4*)(red + (lt+384)*4);
        float zz0 = sig_(p0.x+p0.y+p0.z+p0.w + bzv);
        float zz1 = sig_(p1.x+p1.y+p1.z+p1.w + bzv);
        float rv0 = sig_(p2.x+p2.y+p2.z+p2.w + brv);
        float rv1 = sig_(p3.x+p3.y+p3.z+p3.w + brv);
        float h0o = h_s[orow0 * HPADF + jbase + ocol];
        float h1o = h_s[orow1 * HPADF + jbase + ocol];
        g_rh[(bbase + orow0) * 256 + jbase + ocol] = rv0 * h0o;
        g_rh[(bbase + orow1) * 256 + jbase + ocol] = rv1 * h1o;

        GRP_ARRIVE()                                // A arrive (flag, no atomics)

        #pragma unroll
        for (int i = 0; i < 8; i++) ac[i] = 0;
        float4 xt[4];
        if (t + 1 < SEQLEN) {                       // issue x(t+1) LDGs (MLP=4)
            #pragma unroll
            for (int j = 0; j < 4; j++) {
                int idx = lt + 128*j;
                xt[j] = ((const float4*)X)[(size_t)(bbase + (idx >> 5)) * (SEQLEN * 32)
                                           + (size_t)(t + 1) * 32 + (idx & 31)];
            }
        }
        #pragma unroll 4
        for (int kk = 0; kk < 8; kk++) {            // cand x-part (overlap A)
            int k4 = 64 + kx + kk, kq = kx + kk;
            ulonglong2 v0 = xA[kq], v1 = xB[kq], v2 = xC[kq], v3 = xD[kq];
            ulonglong2 c0 = wcp[k4*16], c1 = wcp[k4*16+8];
            C8(v0,v1,v2,v3,c0,c1)
        }
        GRP_WAIT()                                  // A wait (parallel flag poll)

        {   // rh gather: stage all 8 LDGs first (MLP=8), then 8 STS
            float4 tmp[8];
            #pragma unroll
            for (int j = 0; j < 8; j++) {
                int idx = lt + 128*j;
                tmp[j] = ((const float4*)g_rh)[(bbase + (idx >> 6)) * 64 + (idx & 63)];
            }
            #pragma unroll
            for (int j = 0; j < 8; j++) {
                int idx = lt + 128*j;
                *(float4*)(rh_s + (idx >> 6) * HPADF + (idx & 63) * 4) = tmp[j];
            }
        }
        barn(nb);

        #pragma unroll 4
        for (int kk = 0; kk < 16; kk++) {           // phase2 h-part
            int k4 = kw + kk;
            ulonglong2 v0 = rA[k4], v1 = rB[k4], v2 = rC[k4], v3 = rD[k4];
            ulonglong2 c0 = wcp[k4*16], c1 = wcp[k4*16+8];
            C8(v0,v1,v2,v3,c0,c1)
        }
        #pragma unroll
        for (int i = 0; i < 4; i++)
            #pragma unroll
            for (int e = 0; e < 2; e++) {
                int o = (rr + 4*i) * 16 + 2*cc + e;
                red[(o << 2) + sw] = f2sum(ac[i*2+e]);
            }
        barn(nb);
        float4 q0 = *(float4*)(red + lt*4);
        float4 q1 = *(float4*)(red + (lt+128)*4);
        float c0v = tanh_(q0.x+q0.y+q0.z+q0.w + bcv);
        float c1v = tanh_(q1.x+q1.y+q1.z+q1.w + bcv);
        float hn0 = h0o + zz0 * (c0v - h0o);
        float hn1 = h1o + zz1 * (c1v - h1o);
        g_h[(bbase + orow0) * 256 + jbase + ocol] = hn0;
        g_h[(bbase + orow1) * 256 + jbase + ocol] = hn1;

        GRP_ARRIVE()                                // B arrive

        // overlap B: out stores (fire-and-forget) + park x(t+1) + z/r x-part
        out[((size_t)t * 256 + bbase + orow0) * 256 + jbase + ocol] = hn0;
        out[((size_t)t * 256 + bbase + orow1) * 256 + jbase + ocol] = hn1;
        #pragma unroll
        for (int i = 0; i < 8; i++) { az[i] = 0; ar[i] = 0; }
        if (t + 1 < SEQLEN) {
            #pragma unroll
            for (int j = 0; j < 4; j++) {
                int idx = lt + 128*j;
                *(float4*)(x_s + (idx >> 5) * XPADF + (idx & 31) * 4) = xt[j];
            }
            barn(nb);
            #pragma unroll 4
            for (int kk = 0; kk < 8; kk++) {
                int k4 = 64 + kx + kk, kq = kx + kk;
                ulonglong2 v0 = xA[kq], v1 = xB[kq], v2 = xC[kq], v3 = xD[kq];
                ulonglong2 z0 = wzp[k4*16], z1 = wzp[k4*16+8];
                ulonglong2 r0 = wrp[k4*16], r1 = wrp[k4*16+8];
                ZR16(v0,v1,v2,v3,z0,z1,r0,r1)
            }
        }
        GRP_WAIT()                                  // B wait
        if (t + 1 < SEQLEN) {
            float4 tmp[8];
            #pragma unroll
            for (int j = 0; j < 8; j++) {           // h gather (staged)
                int idx = lt + 128*j;
                tmp[j] = ((const float4*)g_h)[(bbase + (idx >> 6)) * 64 + (idx & 63)];
            }
            #pragma unroll
            for (int j = 0; j < 8; j++) {
                int idx = lt + 128*j;
                *(float4*)(h_s + (idx >> 6) * HPADF + (idx & 63) * 4) = tmp[j];
            }
            barn(nb);
        }
    }
}

extern "C" void kernel_launch(void* const* d_in, const int* in_sizes, int n_in,
                              void* d_out, int out_size) {
    const float* X  = (const float*)d_in[0];
    const float* Wz = (const float*)d_in[1];
    const float* bz = (const float*)d_in[2];
    const float* Wr = (const float*)d_in[3];
    const float* br = (const float*)d_in[4];
    const float* Wc = (const float*)d_in[5];
    const float* bc = (const float*)d_in[6];
    float* out = (float*)d_out;

    int smem_bytes = (18480 + 2 * QBLK) * (int)sizeof(float);   // 173,760 B
    cudaFuncSetAttribute(gru_persistent,
                         cudaFuncAttributeMaxDynamicSharedMemorySize, smem_bytes);
    gru_persistent<<<128, 256, smem_bytes>>>(X, Wz, bz, Wr, br, Wc, bc, out);
}

// round 17
// speedup vs baseline: 1.4619x; 1.4619x over previous
#include <cuda_runtime.h>

// GRU persistent v9 = v5 (best) with a monotonic-counter group barrier:
// single atomicAdd arrive + single poller per CTA on the SAME line,
// no reset, no release hop, no sense flag.
#define SEQLEN 512
#define HPADF  260
#define XPADF  132
#define WT4    1536
#define QBLK   12480

__device__ float              g_h [256 * 256];
__device__ float              g_rh[256 * 256];
__device__ unsigned long long g_cnt[16 * 16];   // [group], 128B apart

__device__ __forceinline__ void ffma2(unsigned long long &a,
                                      unsigned long long x, unsigned long long y) {
    asm("fma.rn.f32x2 %0, %1, %2, %0;" : "+l"(a) : "l"(x), "l"(y));
}
__device__ __forceinline__ float f2sum(unsigned long long v) {
    return __uint_as_float((unsigned)v) + __uint_as_float((unsigned)(v >> 32));
}
__device__ __forceinline__ float sig_(float a) { return 1.0f / (1.0f + __expf(-a)); }
__device__ __forceinline__ float tanh_(float a) { return 2.0f / (1.0f + __expf(-2.0f * a)) - 1.0f; }
__device__ __forceinline__ void barn(int id) {
    asm volatile("bar.sync %0, 128;" :: "r"(id) : "memory");
}

#define ACC2(a, wv, hv) { ffma2(a, (wv).x, (hv).x); ffma2(a, (wv).y, (hv).y); }
#define ZR16(v0,v1,v2,v3,z0,z1,r0,r1) \
    ACC2(az[0],z0,v0); ACC2(az[1],z1,v0); ACC2(az[2],z0,v1); ACC2(az[3],z1,v1); \
    ACC2(az[4],z0,v2); ACC2(az[5],z1,v2); ACC2(az[6],z0,v3); ACC2(az[7],z1,v3); \
    ACC2(ar[0],r0,v0); ACC2(ar[1],r1,v0); ACC2(ar[2],r0,v1); ACC2(ar[3],r1,v1); \
    ACC2(ar[4],r0,v2); ACC2(ar[5],r1,v2); ACC2(ar[6],r0,v3); ACC2(ar[7],r1,v3);
#define C8(v0,v1,v2,v3,c0,c1) \
    ACC2(ac[0],c0,v0); ACC2(ac[1],c1,v0); ACC2(ac[2],c0,v1); ACC2(ac[3],c1,v1); \
    ACC2(ac[4],c0,v2); ACC2(ac[5],c1,v2); ACC2(ac[6],c0,v3); ACC2(ac[7],c1,v3);

// arrive: intra-half barn orders all threads' global writes; thread 0 of the
// half adds 1 to the group's monotonic counter (release via threadfence).
#define GRP_ARRIVE() { barn(nb); bidx++; \
    if (lt == 0) { __threadfence(); atomicAdd(cnt, 1ull); } }
// wait: thread 0 of the half polls the SAME counter (one line, one poller).
#define GRP_WAIT() { \
    if (lt == 0) { \
        while ((long long)(*((volatile unsigned long long *)cnt) - base) \
               < (long long)(16ull * bidx)) { } \
        __threadfence(); \
    } \
    barn(nb); }

__global__ void __launch_bounds__(256, 1)
gru_persistent(const float* __restrict__ X,
               const float* __restrict__ Wz, const float* __restrict__ bz,
               const float* __restrict__ Wr, const float* __restrict__ br,
               const float* __restrict__ Wc, const float* __restrict__ bc,
               float* __restrict__ out)
{
    extern __shared__ float sm[];
    float* wT = sm;                       // 18432 floats, k-major interleaved
    float* sB = sm + 18432;               // 48
    const int tid  = threadIdx.x;
    const int half = tid >> 7, lt = tid & 127;
    const int w = lt >> 5, l = lt & 31, rr = l & 3, cc = l >> 2;
    const int bt = blockIdx.x & 7, hsb = blockIdx.x >> 3;
    const int bbase = bt * 32 + half * 16, jbase = hsb * 16;
    const int nb = 1 + half;
    float* hb   = sm + 18480 + half * QBLK;
    float* h_s  = hb;                     // 16 x 260
    float* rh_s = hb + 4160;              // 16 x 260
    float* x_s  = hb + 8320;              // 16 x 132
    float* red  = hb + 10432;             // 2048

    unsigned long long* cnt = &g_cnt[(bt * 2 + half) * 16];
    unsigned long long base = 0, bidx = 0;
    if (lt == 0) {  // each full run adds exactly 16*1024=16384 per group
        unsigned long long v = *((volatile unsigned long long *)cnt);
        base = (v / 16384ull) * 16384ull;
    }

    {   // weights: k-major, col pairs interleaved (slot = (c>>1) + 8*(c&1))
        float4* wp = (float4*)wT;
        for (int idx = tid; idx < 3 * WT4; idx += 256) {
            int g = idx / WT4, rem = idx % WT4, k4 = rem >> 4, c = rem & 15;
            const float4* W4 = (const float4*)((g == 0) ? Wz : (g == 1) ? Wr : Wc);
            wp[(g * 96 + k4) * 16 + ((c >> 1) + 8 * (c & 1))] = W4[(jbase + c) * 96 + k4];
        }
        if (tid < 16) {
            sB[tid] = bz[jbase + tid]; sB[16 + tid] = br[jbase + tid];
            sB[32 + tid] = bc[jbase + tid];
        }
    }
    for (int i = lt; i < 16 * HPADF; i += 128) h_s[i] = 0.0f;   // h0 = 0
    #pragma unroll
    for (int j = 0; j < 4; j++) {
        int idx = lt + 128 * j, row = idx >> 5, c4 = idx & 31;
        *(float4*)(x_s + row * XPADF + c4 * 4) =
            ((const float4*)X)[(size_t)(bbase + row) * (SEQLEN * 32) + c4];
    }
    __syncthreads();

    const ulonglong2* hA = (const ulonglong2*)(h_s + rr * HPADF);
    const ulonglong2* hB = (const ulonglong2*)(h_s + (rr + 4) * HPADF);
    const ulonglong2* hC = (const ulonglong2*)(h_s + (rr + 8) * HPADF);
    const ulonglong2* hD = (const ulonglong2*)(h_s + (rr + 12) * HPADF);
    const ulonglong2* rA = (const ulonglong2*)(rh_s + rr * HPADF);
    const ulonglong2* rB = (const ulonglong2*)(rh_s + (rr + 4) * HPADF);
    const ulonglong2* rC = (const ulonglong2*)(rh_s + (rr + 8) * HPADF);
    const ulonglong2* rD = (const ulonglong2*)(rh_s + (rr + 12) * HPADF);
    const ulonglong2* xA = (const ulonglong2*)(x_s + rr * XPADF);
    const ulonglong2* xB = (const ulonglong2*)(x_s + (rr + 4) * XPADF);
    const ulonglong2* xC = (const ulonglong2*)(x_s + (rr + 8) * XPADF);
    const ulonglong2* xD = (const ulonglong2*)(x_s + (rr + 12) * XPADF);
    const ulonglong2* wzp = (const ulonglong2*)wT + cc;
    const ulonglong2* wrp = wzp + WT4;
    const ulonglong2* wcp = wzp + 2 * WT4;
    const int kw = w * 16, kx = w * 8, sw = w ^ rr;
    const int orow0 = lt >> 4, ocol = lt & 15, orow1 = orow0 + 8;
    const float bzv = sB[ocol], brv = sB[16 + ocol], bcv = sB[32 + ocol];

    unsigned long long az[8], ar[8], ac[8];
    #pragma unroll
    for (int i = 0; i < 8; i++) { az[i] = 0; ar[i] = 0; }
    #pragma unroll 4
    for (int kk = 0; kk < 8; kk++) {            // z/r x-part, t=0
        int k4 = 64 + kx + kk, kq = kx + kk;
        ulonglong2 v0 = xA[kq], v1 = xB[kq], v2 = xC[kq], v3 = xD[kq];
        ulonglong2 z0 = wzp[k4*16], z1 = wzp[k4*16+8];
        ulonglong2 r0 = wrp[k4*16], r1 = wrp[k4*16+8];
        ZR16(v0,v1,v2,v3,z0,z1,r0,r1)
    }

    // anti-phase stagger: half 1 runs 2 dummy phase1-h passes on zeroed h_s
    // (adds exact zeros to az/ar — numeric identity, offsets the halves).
    if (half == 1) {
        #pragma unroll 1
        for (int d = 0; d < 2; d++) {
            #pragma unroll 4
            for (int kk = 0; kk < 16; kk++) {
                int k4 = kw + kk;
                ulonglong2 v0 = hA[k4], v1 = hB[k4], v2 = hC[k4], v3 = hD[k4];
                ulonglong2 z0 = wzp[k4*16], z1 = wzp[k4*16+8];
                ulonglong2 r0 = wrp[k4*16], r1 = wrp[k4*16+8];
                ZR16(v0,v1,v2,v3,z0,z1,r0,r1)
            }
        }
    }

    for (int t = 0; t < SEQLEN; t++) {
        #pragma unroll 4
        for (int kk = 0; kk < 16; kk++) {       // phase1 h-part
            int k4 = kw + kk;
            ulonglong2 v0 = hA[k4], v1 = hB[k4], v2 = hC[k4], v3 = hD[k4];
            ulonglong2 z0 = wzp[k4*16], z1 = wzp[k4*16+8];
            ulonglong2 r0 = wrp[k4*16], r1 = wrp[k4*16+8];
            ZR16(v0,v1,v2,v3,z0,z1,r0,r1)
        }
        #pragma unroll
        for (int i = 0; i < 4; i++)
            #pragma unroll
            for (int e = 0; e < 2; e++) {
                int o = (rr + 4*i) * 16 + 2*cc + e;
                red[(o << 2) + sw]         = f2sum(az[i*2+e]);
                red[((256 + o) << 2) + sw] = f2sum(ar[i*2+e]);
            }
        barn(nb);
        float4 p0 = *(float4*)(red + lt*4);
        float4 p1 = *(float4*)(red + (lt+128)*4);
        float4 p2 = *(float4*)(red + (lt+256)*4);
        float4 p3 = *(float4*)(red + (lt+384)*4);
        float zz0 = sig_(p0.x+p0.y+p0.z+p0.w + bzv);
        float zz1 = sig_(p1.x+p1.y+p1.z+p1.w + bzv);
        float rv0 = sig_(p2.x+p2.y+p2.z+p2.w + brv);
        float rv1 = sig_(p3.x+p3.y+p3.z+p3.w + brv);
        float h0o = h_s[orow0 * HPADF + jbase + ocol];
        float h1o = h_s[orow1 * HPADF + jbase + ocol];
        g_rh[(bbase + orow0) * 256 + jbase + ocol] = rv0 * h0o;
        g_rh[(bbase + orow1) * 256 + jbase + ocol] = rv1 * h1o;

        GRP_ARRIVE()                                // A arrive

        #pragma unroll
        for (int i = 0; i < 8; i++) ac[i] = 0;
        #pragma unroll 4
        for (int kk = 0; kk < 8; kk++) {            // cand x-part (overlap A)
            int k4 = 64 + kx + kk, kq = kx + kk;
            ulonglong2 v0 = xA[kq], v1 = xB[kq], v2 = xC[kq], v3 = xD[kq];
            ulonglong2 c0 = wcp[k4*16], c1 = wcp[k4*16+8];
            C8(v0,v1,v2,v3,c0,c1)
        }
        GRP_WAIT()                                  // A wait

        {   // rh gather: stage all 8 LDGs first (MLP=8), then 8 STS
            float4 tmp[8];
            #pragma unroll
            for (int j = 0; j < 8; j++) {
                int idx = lt + 128*j;
                tmp[j] = ((const float4*)g_rh)[(bbase + (idx >> 6)) * 64 + (idx & 63)];
            }
            #pragma unroll
            for (int j = 0; j < 8; j++) {
                int idx = lt + 128*j;
                *(float4*)(rh_s + (idx >> 6) * HPADF + (idx & 63) * 4) = tmp[j];
            }
        }
        barn(nb);

        #pragma unroll 4
        for (int kk = 0; kk < 16; kk++) {           // phase2 h-part
            int k4 = kw + kk;
            ulonglong2 v0 = rA[k4], v1 = rB[k4], v2 = rC[k4], v3 = rD[k4];
            ulonglong2 c0 = wcp[k4*16], c1 = wcp[k4*16+8];
            C8(v0,v1,v2,v3,c0,c1)
        }
        #pragma unroll
        for (int i = 0; i < 4; i++)
            #pragma unroll
            for (int e = 0; e < 2; e++) {
                int o = (rr + 4*i) * 16 + 2*cc + e;
                red[(o << 2) + sw] = f2sum(ac[i*2+e]);
            }
        barn(nb);
        float4 q0 = *(float4*)(red + lt*4);
        float4 q1 = *(float4*)(red + (lt+128)*4);
        float c0v = tanh_(q0.x+q0.y+q0.z+q0.w + bcv);
        float c1v = tanh_(q1.x+q1.y+q1.z+q1.w + bcv);
        float hn0 = h0o + zz0 * (c0v - h0o);
        float hn1 = h1o + zz1 * (c1v - h1o);
        g_h[(bbase + orow0) * 256 + jbase + ocol] = hn0;
        g_h[(bbase + orow1) * 256 + jbase + ocol] = hn1;

        GRP_ARRIVE()                                // B arrive

        // overlap B: out stores (fire-and-forget) + x(t+1) + z/r x-part
        out[((size_t)t * 256 + bbase + orow0) * 256 + jbase + ocol] = hn0;
        out[((size_t)t * 256 + bbase + orow1) * 256 + jbase + ocol] = hn1;
        #pragma unroll
        for (int i = 0; i < 8; i++) { az[i] = 0; ar[i] = 0; }
        if (t + 1 < SEQLEN) {
            float4 xt[4];
            #pragma unroll
            for (int j = 0; j < 4; j++) {
                int idx = lt + 128*j;
                xt[j] = ((const float4*)X)[(size_t)(bbase + (idx >> 5)) * (SEQLEN * 32)
                                           + (size_t)(t + 1) * 32 + (idx & 31)];
            }
            #pragma unroll
            for (int j = 0; j < 4; j++) {
                int idx = lt + 128*j;
                *(float4*)(x_s + (idx >> 5) * XPADF + (idx & 31) * 4) = xt[j];
            }
            barn(nb);
            #pragma unroll 4
            for (int kk = 0; kk < 8; kk++) {
                int k4 = 64 + kx + kk, kq = kx + kk;
                ulonglong2 v0 = xA[kq], v1 = xB[kq], v2 = xC[kq], v3 = xD[kq];
                ulonglong2 z0 = wzp[k4*16], z1 = wzp[k4*16+8];
                ulonglong2 r0 = wrp[k4*16], r1 = wrp[k4*16+8];
                ZR16(v0,v1,v2,v3,z0,z1,r0,r1)
            }
        }
        GRP_WAIT()                                  // B wait
        if (t + 1 < SEQLEN) {
            float4 tmp[8];
            #pragma unroll
            for (int j = 0; j < 8; j++) {           // h gather (staged)
                int idx = lt + 128*j;
                tmp[j] = ((const float4*)g_h)[(bbase + (idx >> 6)) * 64 + (idx & 63)];
            }
            #pragma unroll
            for (int j = 0; j < 8; j++) {
                int idx = lt + 128*j;
                *(float4*)(h_s + (idx >> 6) * HPADF + (idx & 63) * 4) = tmp[j];
            }
            barn(nb);
        }
    }
}

extern "C" void kernel_launch(void* const* d_in, const int* in_sizes, int n_in,
                              void* d_out, int out_size) {
    const float* X  = (const float*)d_in[0];
    const float* Wz = (const float*)d_in[1];
    const float* bz = (const float*)d_in[2];
    const float* Wr = (const float*)d_in[3];
    const float* br = (const float*)d_in[4];
    const float* Wc = (const float*)d_in[5];
    const float* bc = (const float*)d_in[6];
    float* out = (float*)d_out;

    int smem_bytes = (18480 + 2 * QBLK) * (int)sizeof(float);   // 173,760 B
    cudaFuncSetAttribute(gru_persistent,
                         cudaFuncAttributeMaxDynamicSharedMemorySize, smem_bytes);
    gru_persistent<<<128, 256, smem_bytes>>>(X, Wz, bz, Wr, br, Wc, bc, out);
}